// round 13
// baseline (speedup 1.0000x reference)
#include <cuda_runtime.h>
#include <cuda_fp16.h>
#include <mma.h>
#include <cstdint>

using namespace nvcuda;

#define BATCH 128
#define MEMSZ 200
#define SENT  50
#define DIM   128
#define VOCAB 50000
#define HOPS  3

typedef long long ll;

// ---------------- scratch (device globals) ------------------------------------
__device__ float  g_m[4ll * BATCH * MEMSZ * DIM];    // m_k for tables 0..3 (fp32)
__device__ float  g_u[BATCH * DIM];                  // u between hops (fp32)
__device__ __half g_uh[BATCH * DIM];                 // final u in fp16
__device__ __half g_C3h[(ll)VOCAB * DIM];            // fp16 copy of table 3
__device__ int    g_is64;

__device__ __forceinline__ int load_idx(const void* p, ll i, int is64) {
    if (is64) return (int)__ldg(((const ll*)p) + i);
    return __ldg(((const int*)p) + i);
}

// ---------------- dtype sniff -------------------------------------------------
__global__ void sniff_kernel(const int* __restrict__ story32, int n32) {
    __shared__ int any;
    if (threadIdx.x == 0) any = 0;
    __syncthreads();
    int lim = n32 < 4001 ? n32 : 4001;
    int local = 0;
    for (int i = 1 + 2 * (int)threadIdx.x; i < lim; i += 2 * (int)blockDim.x)
        local |= __ldg(&story32[i]);
    if (local) atomicOr(&any, 1);
    __syncthreads();
    if (threadIdx.x == 0) g_is64 = (any == 0) ? 1 : 0;
}

// ---------------- table3 fp32 -> fp16 (overlaps gather pass 0 on side stream) -
__global__ void conv3h_kernel(const float* __restrict__ C3) {
    ll i = ((ll)blockIdx.x * blockDim.x + threadIdx.x) * 8;
    if (i >= (ll)VOCAB * DIM) return;
    float4 a = __ldg((const float4*)&C3[i]);
    float4 b = __ldg((const float4*)&C3[i + 4]);
    __half2 h0 = __floats2half2_rn(a.x, a.y);
    __half2 h1 = __floats2half2_rn(a.z, a.w);
    __half2 h2 = __floats2half2_rn(b.x, b.y);
    __half2 h3 = __floats2half2_rn(b.z, b.w);
    uint4 st;
    st.x = *(unsigned*)&h0; st.y = *(unsigned*)&h1;
    st.z = *(unsigned*)&h2; st.w = *(unsigned*)&h3;
    *(uint4*)&g_C3h[i] = st;
}

// ---------------- m_k (fp32 gather, tables 0..2: logit-critical) --------------
__global__ void m_kernel(const void* __restrict__ story, const float* __restrict__ tab,
                         float* __restrict__ mout) {
    int bm   = blockIdx.x;
    int tid  = threadIdx.x;
    int lane = tid & 31, w = tid >> 5;

    __shared__ int    s_off[SENT];          // byte offset into table
    __shared__ float4 part[3][32];

    int is64 = g_is64;
    if (tid < SENT)
        s_off[tid] = load_idx(story, (ll)bm * SENT + tid, is64) * (DIM * 4);
    __syncthreads();

    const int d0 = lane * 4;
    const float cc  = 4.0f / ((float)DIM * (float)SENT);
    const float ed0 = (float)(d0 + 1) - 64.5f;
    const float ed1 = ed0 + 1.0f, ed2 = ed0 + 2.0f, ed3 = ed0 + 3.0f;
    const char* base = (const char*)tab;

    float4 acc = make_float4(0.f, 0.f, 0.f, 0.f);
    for (int s = w; s < SENT; s += 4) {
        float es = (s == SENT - 1) ? 0.0f : ((float)(s + 1) - 25.5f);
        float ce = cc * es;
        float4 v = ((const float4*)(base + s_off[s]))[lane];
        acc.x = fmaf(v.x, fmaf(ce, ed0, 1.0f), acc.x);
        acc.y = fmaf(v.y, fmaf(ce, ed1, 1.0f), acc.y);
        acc.z = fmaf(v.z, fmaf(ce, ed2, 1.0f), acc.z);
        acc.w = fmaf(v.w, fmaf(ce, ed3, 1.0f), acc.w);
    }
    if (w > 0) part[w - 1][lane] = acc;
    __syncthreads();
    if (w == 0) {
        float4 p0 = part[0][lane], p1 = part[1][lane], p2 = part[2][lane];
        acc.x += p0.x + p1.x + p2.x;
        acc.y += p0.y + p1.y + p2.y;
        acc.z += p0.z + p1.z + p2.z;
        acc.w += p0.w + p1.w + p2.w;
        *(float4*)&mout[(ll)bm * DIM + d0] = acc;
    }
}

// ---------------- m_3 (fp16 gather — table 3 never feeds logits) --------------
// 256B rows through LTS instead of 512B; fp32 accumulate; fp32 output.
__global__ void m3_kernel(const void* __restrict__ story, float* __restrict__ mout) {
    int bm   = blockIdx.x;
    int tid  = threadIdx.x;
    int lane = tid & 31, w = tid >> 5;

    __shared__ int    s_off[SENT];          // byte offset into fp16 table
    __shared__ float4 part[3][32];

    int is64 = g_is64;
    if (tid < SENT)
        s_off[tid] = load_idx(story, (ll)bm * SENT + tid, is64) * (DIM * 2);
    __syncthreads();

    const int d0 = lane * 4;
    const float cc  = 4.0f / ((float)DIM * (float)SENT);
    const float ed0 = (float)(d0 + 1) - 64.5f;
    const float ed1 = ed0 + 1.0f, ed2 = ed0 + 2.0f, ed3 = ed0 + 3.0f;
    const char* base = (const char*)g_C3h;

    float4 acc = make_float4(0.f, 0.f, 0.f, 0.f);
    for (int s = w; s < SENT; s += 4) {
        float es = (s == SENT - 1) ? 0.0f : ((float)(s + 1) - 25.5f);
        float ce = cc * es;
        uint2 u = ((const uint2*)(base + s_off[s]))[lane];   // 4 halfs = 8B
        float2 f0 = __half22float2(*(__half2*)&u.x);
        float2 f1 = __half22float2(*(__half2*)&u.y);
        acc.x = fmaf(f0.x, fmaf(ce, ed0, 1.0f), acc.x);
        acc.y = fmaf(f0.y, fmaf(ce, ed1, 1.0f), acc.y);
        acc.z = fmaf(f1.x, fmaf(ce, ed2, 1.0f), acc.z);
        acc.w = fmaf(f1.y, fmaf(ce, ed3, 1.0f), acc.w);
    }
    if (w > 0) part[w - 1][lane] = acc;
    __syncthreads();
    if (w == 0) {
        float4 p0 = part[0][lane], p1 = part[1][lane], p2 = part[2][lane];
        acc.x += p0.x + p1.x + p2.x;
        acc.y += p0.y + p1.y + p2.y;
        acc.z += p0.z + p1.z + p2.z;
        acc.w += p0.w + p1.w + p2.w;
        *(float4*)&mout[(ll)bm * DIM + d0] = acc;
    }
}

// ---------------- u0[b,d] = sum_s C0[query[b,s]][d] * enc(s,d) ---------------
__global__ void u0_kernel(const void* __restrict__ query, const float* __restrict__ C) {
    int b    = blockIdx.x;
    int tid  = threadIdx.x;
    int lane = tid & 31, w = tid >> 5;

    __shared__ int    s_idx[SENT];
    __shared__ float4 part[3][32];

    int is64 = g_is64;
    if (tid < SENT) s_idx[tid] = load_idx(query, (ll)b * SENT + tid, is64);
    __syncthreads();

    const int d0 = lane * 4;
    const float cc  = 4.0f / ((float)DIM * (float)SENT);
    const float ed0 = (float)(d0 + 1) - 64.5f;
    const float ed1 = ed0 + 1.0f, ed2 = ed0 + 2.0f, ed3 = ed0 + 3.0f;

    float4 acc = make_float4(0.f, 0.f, 0.f, 0.f);
    for (int s = w; s < SENT; s += 4) {
        float es = (s == SENT - 1) ? 0.0f : ((float)(s + 1) - 25.5f);
        float ce = cc * es;
        float4 v = __ldg((const float4*)&C[(ll)s_idx[s] * DIM + d0]);
        acc.x = fmaf(v.x, fmaf(ce, ed0, 1.0f), acc.x);
        acc.y = fmaf(v.y, fmaf(ce, ed1, 1.0f), acc.y);
        acc.z = fmaf(v.z, fmaf(ce, ed2, 1.0f), acc.z);
        acc.w = fmaf(v.w, fmaf(ce, ed3, 1.0f), acc.w);
    }
    if (w > 0) part[w - 1][lane] = acc;
    __syncthreads();
    if (w == 0) {
        float4 p0 = part[0][lane], p1 = part[1][lane], p2 = part[2][lane];
        acc.x += p0.x + p1.x + p2.x;
        acc.y += p0.y + p1.y + p2.y;
        acc.z += p0.z + p1.z + p2.z;
        acc.w += p0.w + p1.w + p2.w;
        *(float4*)&g_u[b * DIM + d0] = acc;
    }
}

// ---------------- one hop (overlaps the gather stream) ------------------------
__global__ __launch_bounds__(512, 1)
void hop_kernel(int h, const float* __restrict__ Tw, const float* __restrict__ Tb) {
    __shared__ float  u_sh[DIM];
    __shared__ float  prob[MEMSZ];
    __shared__ float  red[512];
    __shared__ float4 opart[16][32];
    __shared__ float  o_sh[DIM];

    int b    = blockIdx.x;
    int tid  = threadIdx.x;
    int lane = tid & 31, w = tid >> 5;       // 16 warps

    if (tid < DIM) u_sh[tid] = g_u[b * DIM + tid];
    __syncthreads();

    const float* mA = g_m + ((ll)h * BATCH * MEMSZ + (ll)b * MEMSZ) * DIM;
    const float* mC = mA + (ll)BATCH * MEMSZ * DIM;

    float4 us = *(const float4*)&u_sh[lane * 4];
    for (int m = w; m < MEMSZ; m += 16) {
        float4 v = __ldg((const float4*)&mA[(ll)m * DIM + lane * 4]);
        float s = v.x * us.x + v.y * us.y + v.z * us.z + v.w * us.w;
#pragma unroll
        for (int off = 16; off; off >>= 1) s += __shfl_xor_sync(0xffffffffu, s, off);
        if (lane == 0) prob[m] = s;
    }
    __syncthreads();

    float4 r[13];
#pragma unroll
    for (int i = 0; i < 13; ++i) {
        int m = w + i * 16;
        if (m < MEMSZ) r[i] = __ldg((const float4*)&mC[(ll)m * DIM + lane * 4]);
    }

    if (tid < 32) {
        float v[7];
        float mx = -1e30f;
#pragma unroll
        for (int j = 0; j < 7; ++j) {
            int m = tid + j * 32;
            v[j] = (m < MEMSZ) ? prob[m] : -1e30f;
            mx = fmaxf(mx, v[j]);
        }
#pragma unroll
        for (int off = 16; off; off >>= 1)
            mx = fmaxf(mx, __shfl_xor_sync(0xffffffffu, mx, off));
        float sum = 0.0f;
#pragma unroll
        for (int j = 0; j < 7; ++j) { v[j] = expf(v[j] - mx); sum += v[j]; }
#pragma unroll
        for (int off = 16; off; off >>= 1)
            sum += __shfl_xor_sync(0xffffffffu, sum, off);
        float inv = 1.0f / sum;
#pragma unroll
        for (int j = 0; j < 7; ++j) {
            int m = tid + j * 32;
            if (m < MEMSZ) prob[m] = v[j] * inv;
        }
    }
    __syncthreads();

    float4 o = make_float4(0.f, 0.f, 0.f, 0.f);
#pragma unroll
    for (int i = 0; i < 13; ++i) {
        int m = w + i * 16;
        if (m < MEMSZ) {
            float p = prob[m];
            o.x = fmaf(p, r[i].x, o.x); o.y = fmaf(p, r[i].y, o.y);
            o.z = fmaf(p, r[i].z, o.z); o.w = fmaf(p, r[i].w, o.w);
        }
    }
    opart[w][lane] = o;
    __syncthreads();
    if (tid < 32) {
        float4 s = make_float4(0.f, 0.f, 0.f, 0.f);
#pragma unroll
        for (int ww = 0; ww < 16; ++ww) {
            float4 p = opart[ww][tid];
            s.x += p.x; s.y += p.y; s.z += p.z; s.w += p.w;
        }
        *(float4*)&o_sh[tid * 4] = s;
    }
    __syncthreads();

    {
        int d = tid >> 2, q = tid & 3;
        const float* twrow = Tw + (ll)d * DIM + q * 32;
        float part = 0.0f;
#pragma unroll
        for (int j = 0; j < 32; j += 4) {
            float4 tv = __ldg((const float4*)&twrow[j]);
            float4 uv = *(const float4*)&u_sh[q * 32 + j];
            part = fmaf(tv.x, uv.x, part); part = fmaf(tv.y, uv.y, part);
            part = fmaf(tv.z, uv.z, part); part = fmaf(tv.w, uv.w, part);
        }
        red[tid] = part;
    }
    __syncthreads();
    if ((tid & 3) == 0) {
        int d = tid >> 2;
        float t = red[tid] + red[tid + 1] + red[tid + 2] + red[tid + 3] + __ldg(&Tb[d]);
        t = 1.0f / (1.0f + expf(-t));
        float un = (1.0f - t) * u_sh[d] + o_sh[d] * t;
        g_u[b * DIM + d] = un;
        if (h == HOPS - 1) g_uh[b * DIM + d] = __float2half(un);
    }
}

// ---------------- a_hat[b,v] = sum_d u[b,d]*C3h[v,d] via wmma fp16 ------------
// A tile loaded straight from the fp16 table copy (half the read traffic).
__global__ __launch_bounds__(256, 2)
void out_gemm(float* __restrict__ out) {
    extern __shared__ __half sh[];
    __half* As = sh;                 // C3h tile [128][128]
    __half* Bs = sh + 128 * 128;     // uh       [128][128]

    int tid = threadIdx.x;
    int wid = tid >> 5;
    int v0  = blockIdx.x * 128;

    for (int i = tid; i < 128 * 16; i += 256) {
        int row = i >> 4, seg = i & 15;
        if (v0 + row < VOCAB)
            ((uint4*)As)[i] = __ldg(((const uint4*)(g_C3h + (ll)(v0 + row) * DIM)) + seg);
    }
    for (int i = tid; i < 128 * 16; i += 256)
        ((uint4*)Bs)[i] = __ldg(((const uint4*)g_uh) + i);
    __syncthreads();

    wmma::fragment<wmma::accumulator, 16, 16, 16, float> acc[8];
#pragma unroll
    for (int n = 0; n < 8; ++n) wmma::fill_fragment(acc[n], 0.0f);

#pragma unroll
    for (int kt = 0; kt < 8; ++kt) {
        wmma::fragment<wmma::matrix_a, 16, 16, 16, __half, wmma::row_major> af;
        wmma::load_matrix_sync(af, As + (wid * 16) * 128 + kt * 16, 128);
#pragma unroll
        for (int n = 0; n < 8; ++n) {
            wmma::fragment<wmma::matrix_b, 16, 16, 16, __half, wmma::col_major> bf;
            wmma::load_matrix_sync(bf, Bs + (n * 16) * 128 + kt * 16, 128);
            wmma::mma_sync(acc[n], af, bf, acc[n]);
        }
    }

    if (v0 + wid * 16 + 16 <= VOCAB) {
#pragma unroll
        for (int n = 0; n < 8; ++n)
            wmma::store_matrix_sync(out + (ll)(n * 16) * VOCAB + v0 + wid * 16,
                                    acc[n], VOCAB, wmma::mem_col_major);
    }
}

// ---------------- launch: fork-join DAG ---------------------------------------
extern "C" void kernel_launch(void* const* d_in, const int* in_sizes, int n_in,
                              void* d_out, int out_size) {
    const void*  story = d_in[0];                 // [B,M,S] int32 or int64
    const void*  query = d_in[1];                 // [B,S]
    const float* C     = (const float*)d_in[2];   // [4,V,D]
    const float* Tw    = (const float*)d_in[3];   // [D,D]
    const float* Tb    = (const float*)d_in[4];   // [D]
    float* out = (float*)d_out;                   // [B,V]

    cudaFuncSetAttribute(out_gemm, cudaFuncAttributeMaxDynamicSharedMemorySize,
                         2 * 128 * 128 * (int)sizeof(__half));

    cudaStream_t s1;
    cudaStreamCreateWithFlags(&s1, cudaStreamNonBlocking);
    cudaEvent_t ef, ec, e1, e2, e3, ej;
    cudaEventCreateWithFlags(&ef, cudaEventDisableTiming);
    cudaEventCreateWithFlags(&ec, cudaEventDisableTiming);
    cudaEventCreateWithFlags(&e1, cudaEventDisableTiming);
    cudaEventCreateWithFlags(&e2, cudaEventDisableTiming);
    cudaEventCreateWithFlags(&e3, cudaEventDisableTiming);
    cudaEventCreateWithFlags(&ej, cudaEventDisableTiming);

    float* g_m_ptr;
    cudaGetSymbolAddress((void**)&g_m_ptr, g_m);
    const ll MSTR = (ll)BATCH * MEMSZ * DIM;

    // main stream: sniff -> 3 fp32 gather passes -> fp16 pass for table 3
    sniff_kernel<<<1, 256>>>((const int*)story, in_sizes[0]);
    cudaEventRecord(ef, 0);
    cudaStreamWaitEvent(s1, ef, 0);                 // fork

    // side stream: u0 + table-3 fp16 conversion overlap gather passes 0/1
    u0_kernel<<<BATCH, 128, 0, s1>>>(query, C);
    {
        ll n8 = ((ll)VOCAB * DIM) / 8;
        conv3h_kernel<<<(int)((n8 + 255) / 256), 256, 0, s1>>>(C + 3ll * VOCAB * DIM);
    }
    cudaEventRecord(ec, s1);                        // C3h ready

    m_kernel<<<BATCH * MEMSZ, 128>>>(story, C + 0ll * VOCAB * DIM, g_m_ptr + 0 * MSTR);
    m_kernel<<<BATCH * MEMSZ, 128>>>(story, C + 1ll * VOCAB * DIM, g_m_ptr + 1 * MSTR);
    cudaEventRecord(e1, 0);                         // m0,m1 ready
    m_kernel<<<BATCH * MEMSZ, 128>>>(story, C + 2ll * VOCAB * DIM, g_m_ptr + 2 * MSTR);
    cudaEventRecord(e2, 0);                         // m2 ready
    cudaStreamWaitEvent(0, ec, 0);                  // need C3h before fp16 gather
    m3_kernel<<<BATCH * MEMSZ, 128>>>(story, g_m_ptr + 3 * MSTR);
    cudaEventRecord(e3, 0);                         // m3 ready

    // side stream: hops fire as their tables land
    cudaStreamWaitEvent(s1, e1, 0);
    hop_kernel<<<BATCH, 512, 0, s1>>>(0, Tw, Tb);
    cudaStreamWaitEvent(s1, e2, 0);
    hop_kernel<<<BATCH, 512, 0, s1>>>(1, Tw, Tb);
    cudaStreamWaitEvent(s1, e3, 0);
    hop_kernel<<<BATCH, 512, 0, s1>>>(2, Tw, Tb);

    out_gemm<<<(VOCAB + 127) / 128, 256, 2 * 128 * 128 * sizeof(__half), s1>>>(out);

    cudaEventRecord(ej, s1);
    cudaStreamWaitEvent(0, ej, 0);                  // join
}

// round 15
// speedup vs baseline: 1.1606x; 1.1606x over previous
#include <cuda_runtime.h>
#include <cuda_fp16.h>
#include <mma.h>
#include <cstdint>

using namespace nvcuda;

#define BATCH 128
#define MEMSZ 200
#define SENT  50
#define DIM   128
#define VOCAB 50000
#define HOPS  3

typedef long long ll;

// ---------------- scratch (device globals) ------------------------------------
__device__ float  g_m[4ll * BATCH * MEMSZ * DIM];    // slots 1..3 used (tables 1..3)
__device__ float  g_u[BATCH * DIM];                  // u between hops (fp32)
__device__ __half g_uh[BATCH * DIM];                 // final u in fp16
__device__ float  g_PR[256ll * VOCAB];               // P rows [0,128) , R rows [128,256)
__device__ int    g_is64;

__device__ __forceinline__ int load_idx(const void* p, ll i, int is64) {
    if (is64) return (int)__ldg(((const ll*)p) + i);
    return __ldg(((const int*)p) + i);
}

// ---------------- dtype sniff -------------------------------------------------
__global__ void sniff_kernel(const int* __restrict__ story32, int n32) {
    __shared__ int any;
    if (threadIdx.x == 0) any = 0;
    __syncthreads();
    int lim = n32 < 4001 ? n32 : 4001;
    int local = 0;
    for (int i = 1 + 2 * (int)threadIdx.x; i < lim; i += 2 * (int)blockDim.x)
        local |= __ldg(&story32[i]);
    if (local) atomicOr(&any, 1);
    __syncthreads();
    if (threadIdx.x == 0) g_is64 = (any == 0) ? 1 : 0;
}

// ---------------- m_k (fp32 gather, tables 1..3) ------------------------------
__global__ void m_kernel(const void* __restrict__ story, const float* __restrict__ tab,
                         float* __restrict__ mout) {
    int bm   = blockIdx.x;
    int tid  = threadIdx.x;
    int lane = tid & 31, w = tid >> 5;

    __shared__ int    s_off[SENT];          // byte offset into table
    __shared__ float4 part[3][32];

    int is64 = g_is64;
    if (tid < SENT)
        s_off[tid] = load_idx(story, (ll)bm * SENT + tid, is64) * (DIM * 4);
    __syncthreads();

    const int d0 = lane * 4;
    const float cc  = 4.0f / ((float)DIM * (float)SENT);
    const float ed0 = (float)(d0 + 1) - 64.5f;
    const float ed1 = ed0 + 1.0f, ed2 = ed0 + 2.0f, ed3 = ed0 + 3.0f;
    const char* base = (const char*)tab;

    float4 acc = make_float4(0.f, 0.f, 0.f, 0.f);
    for (int s = w; s < SENT; s += 4) {
        float es = (s == SENT - 1) ? 0.0f : ((float)(s + 1) - 25.5f);
        float ce = cc * es;
        float4 v = ((const float4*)(base + s_off[s]))[lane];
        acc.x = fmaf(v.x, fmaf(ce, ed0, 1.0f), acc.x);
        acc.y = fmaf(v.y, fmaf(ce, ed1, 1.0f), acc.y);
        acc.z = fmaf(v.z, fmaf(ce, ed2, 1.0f), acc.z);
        acc.w = fmaf(v.w, fmaf(ce, ed3, 1.0f), acc.w);
    }
    if (w > 0) part[w - 1][lane] = acc;
    __syncthreads();
    if (w == 0) {
        float4 p0 = part[0][lane], p1 = part[1][lane], p2 = part[2][lane];
        acc.x += p0.x + p1.x + p2.x;
        acc.y += p0.y + p1.y + p2.y;
        acc.z += p0.z + p1.z + p2.z;
        acc.w += p0.w + p1.w + p2.w;
        *(float4*)&mout[(ll)bm * DIM + d0] = acc;
    }
}

// ---------------- u0[b,d] = sum_s C0[query[b,s]][d] * enc(s,d) ---------------
__global__ void u0_kernel(const void* __restrict__ query, const float* __restrict__ C) {
    int b    = blockIdx.x;
    int tid  = threadIdx.x;
    int lane = tid & 31, w = tid >> 5;

    __shared__ int    s_idx[SENT];
    __shared__ float4 part[3][32];

    int is64 = g_is64;
    if (tid < SENT) s_idx[tid] = load_idx(query, (ll)b * SENT + tid, is64);
    __syncthreads();

    const int d0 = lane * 4;
    const float cc  = 4.0f / ((float)DIM * (float)SENT);
    const float ed0 = (float)(d0 + 1) - 64.5f;
    const float ed1 = ed0 + 1.0f, ed2 = ed0 + 2.0f, ed3 = ed0 + 3.0f;

    float4 acc = make_float4(0.f, 0.f, 0.f, 0.f);
    for (int s = w; s < SENT; s += 4) {
        float es = (s == SENT - 1) ? 0.0f : ((float)(s + 1) - 25.5f);
        float ce = cc * es;
        float4 v = __ldg((const float4*)&C[(ll)s_idx[s] * DIM + d0]);
        acc.x = fmaf(v.x, fmaf(ce, ed0, 1.0f), acc.x);
        acc.y = fmaf(v.y, fmaf(ce, ed1, 1.0f), acc.y);
        acc.z = fmaf(v.z, fmaf(ce, ed2, 1.0f), acc.z);
        acc.w = fmaf(v.w, fmaf(ce, ed3, 1.0f), acc.w);
    }
    if (w > 0) part[w - 1][lane] = acc;
    __syncthreads();
    if (w == 0) {
        float4 p0 = part[0][lane], p1 = part[1][lane], p2 = part[2][lane];
        acc.x += p0.x + p1.x + p2.x;
        acc.y += p0.y + p1.y + p2.y;
        acc.z += p0.z + p1.z + p2.z;
        acc.w += p0.w + p1.w + p2.w;
        *(float4*)&g_u[b * DIM + d0] = acc;
    }
}

// ---------------- PR sgemm: P/R[b,t] from C0 @ [u0 | ed*u0] -------------------
// grid (391, 2): ny=0 -> P (B = u0), ny=1 -> R (B = ed .* u0). fp32 FFMA
// (logit-critical — must stay fp32). C0 streamed (__ldcs), PR streamed (__stcs).
#define GV 128
#define DK 32
__global__ __launch_bounds__(256, 2)
void pr_gemm(const float* __restrict__ C0) {
    __shared__ float Csh[DK][GV + 4];
    __shared__ float Ush[DK][BATCH + 4];

    int tid = threadIdx.x;
    int tx = tid & 15, ty = tid >> 4;
    int v0 = blockIdx.x * GV;
    int ny = blockIdx.y;

    float acc[8][8];
#pragma unroll
    for (int j = 0; j < 8; ++j)
#pragma unroll
        for (int i = 0; i < 8; ++i) acc[j][i] = 0.0f;

    for (int k0 = 0; k0 < DIM; k0 += DK) {
#pragma unroll
        for (int i = tid; i < DK * GV; i += 256) {
            int kk = i & (DK - 1);
            int vv = i >> 5;
            int v = v0 + vv;
            Csh[kk][vv] = (v < VOCAB) ? __ldcs(&C0[(ll)v * DIM + k0 + kk]) : 0.0f;
            float uv = g_u[vv * DIM + k0 + kk];
            if (ny) uv *= ((float)(k0 + kk + 1) - 64.5f);   // ed(d)
            Ush[kk][vv] = uv;
        }
        __syncthreads();
#pragma unroll
        for (int kk = 0; kk < DK; ++kk) {
            float a[8], bb[8];
#pragma unroll
            for (int i = 0; i < 8; ++i) a[i]  = Csh[kk][tx * 8 + i];
#pragma unroll
            for (int j = 0; j < 8; ++j) bb[j] = Ush[kk][ty * 8 + j];
#pragma unroll
            for (int j = 0; j < 8; ++j)
#pragma unroll
                for (int i = 0; i < 8; ++i) acc[j][i] = fmaf(a[i], bb[j], acc[j][i]);
        }
        __syncthreads();
    }

#pragma unroll
    for (int j = 0; j < 8; ++j) {
        int n = ny * 128 + ty * 8 + j;
#pragma unroll
        for (int i = 0; i < 8; i += 4) {
            int v = v0 + tx * 8 + i;
            if (v + 3 < VOCAB) {
                float4 st = make_float4(acc[j][i], acc[j][i+1], acc[j][i+2], acc[j][i+3]);
                __stcs((float4*)&g_PR[(ll)n * VOCAB + v], st);
            } else {
                for (int q = 0; q < 4; ++q)
                    if (v + q < VOCAB) g_PR[(ll)n * VOCAB + v + q] = acc[j][i + q];
            }
        }
    }
}

// ---------------- hop 0: scores from PR lookup; o from m1 ---------------------
__global__ __launch_bounds__(512, 1)
void hop0_kernel(const void* __restrict__ story,
                 const float* __restrict__ Tw, const float* __restrict__ Tb) {
    __shared__ float  u_sh[DIM];
    __shared__ float  prob[MEMSZ];
    __shared__ float  red[512];
    __shared__ float4 opart[16][32];
    __shared__ float  o_sh[DIM];

    int b    = blockIdx.x;
    int tid  = threadIdx.x;
    int lane = tid & 31, w = tid >> 5;       // 16 warps

    if (tid < DIM) u_sh[tid] = g_u[b * DIM + tid];
    __syncthreads();

    int is64 = g_is64;
    const float cc = 4.0f / ((float)DIM * (float)SENT);
    const float* Pb = g_PR + (ll)b * VOCAB;
    const float* Rb = g_PR + (ll)(128 + b) * VOCAB;
    const float* mC = g_m + (1ll * BATCH * MEMSZ + (ll)b * MEMSZ) * DIM;   // table 1

    // ---- scores: score[m] = sum_s P[b,tok] + cc*es(s)*R[b,tok] ----
    for (int m = w; m < MEMSZ; m += 16) {
        float sc = 0.0f;
#pragma unroll
        for (int rep = 0; rep < 2; ++rep) {
            int s = lane + rep * 32;
            if (s < SENT) {
                int t = load_idx(story, ((ll)b * MEMSZ + m) * SENT + s, is64);
                float P = __ldg(&Pb[t]);
                float R = __ldg(&Rb[t]);
                float es = (s == SENT - 1) ? 0.0f : ((float)(s + 1) - 25.5f);
                sc += fmaf(cc * es, R, P);
            }
        }
#pragma unroll
        for (int off = 16; off; off >>= 1) sc += __shfl_xor_sync(0xffffffffu, sc, off);
        if (lane == 0) prob[m] = sc;
    }
    __syncthreads();

    // ---- prefetch mC rows ----
    float4 r[13];
#pragma unroll
    for (int i = 0; i < 13; ++i) {
        int m = w + i * 16;
        if (m < MEMSZ) r[i] = __ldg((const float4*)&mC[(ll)m * DIM + lane * 4]);
    }

    // ---- softmax (single warp) ----
    if (tid < 32) {
        float v[7];
        float mx = -1e30f;
#pragma unroll
        for (int j = 0; j < 7; ++j) {
            int m = tid + j * 32;
            v[j] = (m < MEMSZ) ? prob[m] : -1e30f;
            mx = fmaxf(mx, v[j]);
        }
#pragma unroll
        for (int off = 16; off; off >>= 1)
            mx = fmaxf(mx, __shfl_xor_sync(0xffffffffu, mx, off));
        float sum = 0.0f;
#pragma unroll
        for (int j = 0; j < 7; ++j) { v[j] = expf(v[j] - mx); sum += v[j]; }
#pragma unroll
        for (int off = 16; off; off >>= 1)
            sum += __shfl_xor_sync(0xffffffffu, sum, off);
        float inv = 1.0f / sum;
#pragma unroll
        for (int j = 0; j < 7; ++j) {
            int m = tid + j * 32;
            if (m < MEMSZ) prob[m] = v[j] * inv;
        }
    }
    __syncthreads();

    // ---- o accumulation ----
    float4 o = make_float4(0.f, 0.f, 0.f, 0.f);
#pragma unroll
    for (int i = 0; i < 13; ++i) {
        int m = w + i * 16;
        if (m < MEMSZ) {
            float p = prob[m];
            o.x = fmaf(p, r[i].x, o.x); o.y = fmaf(p, r[i].y, o.y);
            o.z = fmaf(p, r[i].z, o.z); o.w = fmaf(p, r[i].w, o.w);
        }
    }
    opart[w][lane] = o;
    __syncthreads();
    if (tid < 32) {
        float4 s = make_float4(0.f, 0.f, 0.f, 0.f);
#pragma unroll
        for (int ww = 0; ww < 16; ++ww) {
            float4 p = opart[ww][tid];
            s.x += p.x; s.y += p.y; s.z += p.z; s.w += p.w;
        }
        *(float4*)&o_sh[tid * 4] = s;
    }
    __syncthreads();

    // ---- gate ----
    {
        int d = tid >> 2, q = tid & 3;
        const float* twrow = Tw + (ll)d * DIM + q * 32;
        float part = 0.0f;
#pragma unroll
        for (int j = 0; j < 32; j += 4) {
            float4 tv = __ldg((const float4*)&twrow[j]);
            float4 uv = *(const float4*)&u_sh[q * 32 + j];
            part = fmaf(tv.x, uv.x, part); part = fmaf(tv.y, uv.y, part);
            part = fmaf(tv.z, uv.z, part); part = fmaf(tv.w, uv.w, part);
        }
        red[tid] = part;
    }
    __syncthreads();
    if ((tid & 3) == 0) {
        int d = tid >> 2;
        float t = red[tid] + red[tid + 1] + red[tid + 2] + red[tid + 3] + __ldg(&Tb[d]);
        t = 1.0f / (1.0f + expf(-t));
        g_u[b * DIM + d] = (1.0f - t) * u_sh[d] + o_sh[d] * t;
    }
}

// ---------------- hops 1,2 (mA = g_m[h], mC = g_m[h+1]) -----------------------
__global__ __launch_bounds__(512, 1)
void hop_kernel(int h, const float* __restrict__ Tw, const float* __restrict__ Tb) {
    __shared__ float  u_sh[DIM];
    __shared__ float  prob[MEMSZ];
    __shared__ float  red[512];
    __shared__ float4 opart[16][32];
    __shared__ float  o_sh[DIM];

    int b    = blockIdx.x;
    int tid  = threadIdx.x;
    int lane = tid & 31, w = tid >> 5;

    if (tid < DIM) u_sh[tid] = g_u[b * DIM + tid];
    __syncthreads();

    const float* mA = g_m + ((ll)h * BATCH * MEMSZ + (ll)b * MEMSZ) * DIM;
    const float* mC = mA + (ll)BATCH * MEMSZ * DIM;

    float4 us = *(const float4*)&u_sh[lane * 4];
    for (int m = w; m < MEMSZ; m += 16) {
        float4 v = __ldg((const float4*)&mA[(ll)m * DIM + lane * 4]);
        float s = v.x * us.x + v.y * us.y + v.z * us.z + v.w * us.w;
#pragma unroll
        for (int off = 16; off; off >>= 1) s += __shfl_xor_sync(0xffffffffu, s, off);
        if (lane == 0) prob[m] = s;
    }
    __syncthreads();

    float4 r[13];
#pragma unroll
    for (int i = 0; i < 13; ++i) {
        int m = w + i * 16;
        if (m < MEMSZ) r[i] = __ldg((const float4*)&mC[(ll)m * DIM + lane * 4]);
    }

    if (tid < 32) {
        float v[7];
        float mx = -1e30f;
#pragma unroll
        for (int j = 0; j < 7; ++j) {
            int m = tid + j * 32;
            v[j] = (m < MEMSZ) ? prob[m] : -1e30f;
            mx = fmaxf(mx, v[j]);
        }
#pragma unroll
        for (int off = 16; off; off >>= 1)
            mx = fmaxf(mx, __shfl_xor_sync(0xffffffffu, mx, off));
        float sum = 0.0f;
#pragma unroll
        for (int j = 0; j < 7; ++j) { v[j] = expf(v[j] - mx); sum += v[j]; }
#pragma unroll
        for (int off = 16; off; off >>= 1)
            sum += __shfl_xor_sync(0xffffffffu, sum, off);
        float inv = 1.0f / sum;
#pragma unroll
        for (int j = 0; j < 7; ++j) {
            int m = tid + j * 32;
            if (m < MEMSZ) prob[m] = v[j] * inv;
        }
    }
    __syncthreads();

    float4 o = make_float4(0.f, 0.f, 0.f, 0.f);
#pragma unroll
    for (int i = 0; i < 13; ++i) {
        int m = w + i * 16;
        if (m < MEMSZ) {
            float p = prob[m];
            o.x = fmaf(p, r[i].x, o.x); o.y = fmaf(p, r[i].y, o.y);
            o.z = fmaf(p, r[i].z, o.z); o.w = fmaf(p, r[i].w, o.w);
        }
    }
    opart[w][lane] = o;
    __syncthreads();
    if (tid < 32) {
        float4 s = make_float4(0.f, 0.f, 0.f, 0.f);
#pragma unroll
        for (int ww = 0; ww < 16; ++ww) {
            float4 p = opart[ww][tid];
            s.x += p.x; s.y += p.y; s.z += p.z; s.w += p.w;
        }
        *(float4*)&o_sh[tid * 4] = s;
    }
    __syncthreads();

    {
        int d = tid >> 2, q = tid & 3;
        const float* twrow = Tw + (ll)d * DIM + q * 32;
        float part = 0.0f;
#pragma unroll
        for (int j = 0; j < 32; j += 4) {
            float4 tv = __ldg((const float4*)&twrow[j]);
            float4 uv = *(const float4*)&u_sh[q * 32 + j];
            part = fmaf(tv.x, uv.x, part); part = fmaf(tv.y, uv.y, part);
            part = fmaf(tv.z, uv.z, part); part = fmaf(tv.w, uv.w, part);
        }
        red[tid] = part;
    }
    __syncthreads();
    if ((tid & 3) == 0) {
        int d = tid >> 2;
        float t = red[tid] + red[tid + 1] + red[tid + 2] + red[tid + 3] + __ldg(&Tb[d]);
        t = 1.0f / (1.0f + expf(-t));
        float un = (1.0f - t) * u_sh[d] + o_sh[d] * t;
        g_u[b * DIM + d] = un;
        if (h == HOPS - 1) g_uh[b * DIM + d] = __float2half(un);
    }
}

// ---------------- a_hat[b,v] = sum_d u[b,d]*C3[v,d] via wmma fp16 -------------
__global__ __launch_bounds__(256, 2)
void out_gemm(const float* __restrict__ C3, float* __restrict__ out) {
    extern __shared__ __half sh[];
    __half* As = sh;                 // C3 tile as fp16 [128][128]
    __half* Bs = sh + 128 * 128;     // uh            [128][128]

    int tid = threadIdx.x;
    int wid = tid >> 5;
    int v0  = blockIdx.x * 128;

    for (int i = tid; i < 128 * 32; i += 256) {
        int row = i >> 5, seg = i & 31;
        if (v0 + row < VOCAB) {
            float4 f = __ldg((const float4*)&C3[(ll)(v0 + row) * DIM + seg * 4]);
            __half2 h0 = __floats2half2_rn(f.x, f.y);
            __half2 h1 = __floats2half2_rn(f.z, f.w);
            uint2 st;
            st.x = *(unsigned*)&h0; st.y = *(unsigned*)&h1;
            *(uint2*)&As[row * 128 + seg * 4] = st;
        }
    }
    for (int i = tid; i < 128 * 16; i += 256)
        ((uint4*)Bs)[i] = __ldg(((const uint4*)g_uh) + i);
    __syncthreads();

    wmma::fragment<wmma::accumulator, 16, 16, 16, float> acc[8];
#pragma unroll
    for (int n = 0; n < 8; ++n) wmma::fill_fragment(acc[n], 0.0f);

#pragma unroll
    for (int kt = 0; kt < 8; ++kt) {
        wmma::fragment<wmma::matrix_a, 16, 16, 16, __half, wmma::row_major> af;
        wmma::load_matrix_sync(af, As + (wid * 16) * 128 + kt * 16, 128);
#pragma unroll
        for (int n = 0; n < 8; ++n) {
            wmma::fragment<wmma::matrix_b, 16, 16, 16, __half, wmma::col_major> bf;
            wmma::load_matrix_sync(bf, Bs + (n * 16) * 128 + kt * 16, 128);
            wmma::mma_sync(acc[n], af, bf, acc[n]);
        }
    }

    if (v0 + wid * 16 + 16 <= VOCAB) {
#pragma unroll
        for (int n = 0; n < 8; ++n)
            wmma::store_matrix_sync(out + (ll)(n * 16) * VOCAB + v0 + wid * 16,
                                    acc[n], VOCAB, wmma::mem_col_major);
    }
}

// ---------------- launch: fork-join DAG (3 gathers + overlapped PR gemm) ------
extern "C" void kernel_launch(void* const* d_in, const int* in_sizes, int n_in,
                              void* d_out, int out_size) {
    const void*  story = d_in[0];                 // [B,M,S] int32 or int64
    const void*  query = d_in[1];                 // [B,S]
    const float* C     = (const float*)d_in[2];   // [4,V,D]
    const float* Tw    = (const float*)d_in[3];   // [D,D]
    const float* Tb    = (const float*)d_in[4];   // [D]
    float* out = (float*)d_out;                   // [B,V]

    cudaFuncSetAttribute(out_gemm, cudaFuncAttributeMaxDynamicSharedMemorySize,
                         2 * 128 * 128 * (int)sizeof(__half));

    cudaStream_t s1;
    cudaStreamCreateWithFlags(&s1, cudaStreamNonBlocking);
    cudaEvent_t ef, e1, e2, e3, ej;
    cudaEventCreateWithFlags(&ef, cudaEventDisableTiming);
    cudaEventCreateWithFlags(&e1, cudaEventDisableTiming);
    cudaEventCreateWithFlags(&e2, cudaEventDisableTiming);
    cudaEventCreateWithFlags(&e3, cudaEventDisableTiming);
    cudaEventCreateWithFlags(&ej, cudaEventDisableTiming);

    float* g_m_ptr;
    cudaGetSymbolAddress((void**)&g_m_ptr, g_m);
    const ll MSTR = (ll)BATCH * MEMSZ * DIM;

    // main stream: sniff -> gathers for tables 1..3 (table 0 eliminated)
    sniff_kernel<<<1, 256>>>((const int*)story, in_sizes[0]);
    cudaEventRecord(ef, 0);
    cudaStreamWaitEvent(s1, ef, 0);                 // fork

    // side stream: u0, then the PR sgemm (overlaps m1/m2 gathers; FMA-bound)
    u0_kernel<<<BATCH, 128, 0, s1>>>(query, C);
    pr_gemm<<<dim3((VOCAB + GV - 1) / GV, 2), 256, 0, s1>>>(C);   // table 0

    m_kernel<<<BATCH * MEMSZ, 128>>>(story, C + 1ll * VOCAB * DIM, g_m_ptr + 1 * MSTR);
    cudaEventRecord(e1, 0);                         // m1 ready
    m_kernel<<<BATCH * MEMSZ, 128>>>(story, C + 2ll * VOCAB * DIM, g_m_ptr + 2 * MSTR);
    cudaEventRecord(e2, 0);                         // m2 ready
    m_kernel<<<BATCH * MEMSZ, 128>>>(story, C + 3ll * VOCAB * DIM, g_m_ptr + 3 * MSTR);
    cudaEventRecord(e3, 0);                         // m3 ready

    // side stream: hop0 (PR + m1), hop1 (m1+m2), hop2 (m2+m3), gemm
    cudaStreamWaitEvent(s1, e1, 0);
    hop0_kernel<<<BATCH, 512, 0, s1>>>(story, Tw, Tb);
    cudaStreamWaitEvent(s1, e2, 0);
    hop_kernel<<<BATCH, 512, 0, s1>>>(1, Tw, Tb);
    cudaStreamWaitEvent(s1, e3, 0);
    hop_kernel<<<BATCH, 512, 0, s1>>>(2, Tw, Tb);

    out_gemm<<<(VOCAB + 127) / 128, 256, 2 * 128 * 128 * sizeof(__half), s1>>>(
        C + 3ll * VOCAB * DIM, out);

    cudaEventRecord(ej, s1);
    cudaStreamWaitEvent(0, ej, 0);                  // join
}

// round 16
// speedup vs baseline: 1.3471x; 1.1607x over previous
#include <cuda_runtime.h>
#include <cuda_fp16.h>
#include <mma.h>
#include <cstdint>

using namespace nvcuda;

#define BATCH 128
#define MEMSZ 200
#define SENT  50
#define DIM   128
#define VOCAB 50000
#define HOPS  3

typedef long long ll;

// ---------------- scratch (device globals) ------------------------------------
__device__ float  g_m[4ll * BATCH * MEMSZ * DIM];    // m_k for tables 0..3 (fp32)
__device__ float  g_u[BATCH * DIM];                  // u between hops (fp32)
__device__ __half g_uh[BATCH * DIM];                 // final u in fp16
__device__ int    g_is64;

__device__ __forceinline__ int load_idx(const void* p, ll i, int is64) {
    if (is64) return (int)__ldg(((const ll*)p) + i);
    return __ldg(((const int*)p) + i);
}

// ---------------- dtype sniff -------------------------------------------------
__global__ void sniff_kernel(const int* __restrict__ story32, int n32) {
    __shared__ int any;
    if (threadIdx.x == 0) any = 0;
    __syncthreads();
    int lim = n32 < 4001 ? n32 : 4001;
    int local = 0;
    for (int i = 1 + 2 * (int)threadIdx.x; i < lim; i += 2 * (int)blockDim.x)
        local |= __ldg(&story32[i]);
    if (local) atomicOr(&any, 1);
    __syncthreads();
    if (threadIdx.x == 0) g_is64 = (any == 0) ? 1 : 0;
}

// ---------------- m_k[b,m,d] = sum_s C_k[story[b,m,s]][d] * enc(s,d) ----------
// fp32 gather — LTS-capped. 256 threads handle TWO (b,m) pairs (warps 0-3 /
// 4-7) to halve block count and shorten the tail wave. grid.y = table index
// offset by ktab0.
__global__ void m_kernel(const void* __restrict__ story, const float* __restrict__ C,
                         int ktab0, float* __restrict__ gm) {
    int tid  = threadIdx.x;
    int lane = tid & 31, w = tid >> 5;         // 8 warps
    int half = w >> 2;                          // 0 or 1: which bm pair member
    int wl   = w & 3;                           // warp-within-half
    int k    = ktab0 + blockIdx.y;
    ll  bm   = (ll)blockIdx.x * 2 + half;

    __shared__ int    s_off[2][SENT];          // byte offsets into table
    __shared__ float4 part[2][3][32];

    int is64 = g_is64;
    if (tid < 2 * SENT) {
        int hh = tid / SENT, ss = tid % SENT;
        ll bm2 = (ll)blockIdx.x * 2 + hh;
        s_off[hh][ss] = load_idx(story, bm2 * SENT + ss, is64) * (DIM * 4);
    }
    __syncthreads();

    const int d0 = lane * 4;
    const float cc  = 4.0f / ((float)DIM * (float)SENT);
    const float ed0 = (float)(d0 + 1) - 64.5f;
    const float ed1 = ed0 + 1.0f, ed2 = ed0 + 2.0f, ed3 = ed0 + 3.0f;
    const char* base = (const char*)(C + (ll)k * VOCAB * DIM);
    const int* soff = s_off[half];

    float4 acc = make_float4(0.f, 0.f, 0.f, 0.f);
    for (int s = wl; s < SENT; s += 4) {
        float es = (s == SENT - 1) ? 0.0f : ((float)(s + 1) - 25.5f);
        float ce = cc * es;
        float4 v = ((const float4*)(base + soff[s]))[lane];
        acc.x = fmaf(v.x, fmaf(ce, ed0, 1.0f), acc.x);
        acc.y = fmaf(v.y, fmaf(ce, ed1, 1.0f), acc.y);
        acc.z = fmaf(v.z, fmaf(ce, ed2, 1.0f), acc.z);
        acc.w = fmaf(v.w, fmaf(ce, ed3, 1.0f), acc.w);
    }
    if (wl > 0) part[half][wl - 1][lane] = acc;
    __syncthreads();
    if (wl == 0) {
        float4 p0 = part[half][0][lane], p1 = part[half][1][lane], p2 = part[half][2][lane];
        acc.x += p0.x + p1.x + p2.x;
        acc.y += p0.y + p1.y + p2.y;
        acc.z += p0.z + p1.z + p2.z;
        acc.w += p0.w + p1.w + p2.w;
        *(float4*)&gm[((ll)k * (BATCH * MEMSZ) + bm) * DIM + d0] = acc;
    }
}

// ---------------- u0[b,d] = sum_s C0[query[b,s]][d] * enc(s,d) ---------------
__global__ void u0_kernel(const void* __restrict__ query, const float* __restrict__ C) {
    int b    = blockIdx.x;
    int tid  = threadIdx.x;
    int lane = tid & 31, w = tid >> 5;

    __shared__ int    s_idx[SENT];
    __shared__ float4 part[3][32];

    int is64 = g_is64;
    if (tid < SENT) s_idx[tid] = load_idx(query, (ll)b * SENT + tid, is64);
    __syncthreads();

    const int d0 = lane * 4;
    const float cc  = 4.0f / ((float)DIM * (float)SENT);
    const float ed0 = (float)(d0 + 1) - 64.5f;
    const float ed1 = ed0 + 1.0f, ed2 = ed0 + 2.0f, ed3 = ed0 + 3.0f;

    float4 acc = make_float4(0.f, 0.f, 0.f, 0.f);
    for (int s = w; s < SENT; s += 4) {
        float es = (s == SENT - 1) ? 0.0f : ((float)(s + 1) - 25.5f);
        float ce = cc * es;
        float4 v = __ldg((const float4*)&C[(ll)s_idx[s] * DIM + d0]);
        acc.x = fmaf(v.x, fmaf(ce, ed0, 1.0f), acc.x);
        acc.y = fmaf(v.y, fmaf(ce, ed1, 1.0f), acc.y);
        acc.z = fmaf(v.z, fmaf(ce, ed2, 1.0f), acc.z);
        acc.w = fmaf(v.w, fmaf(ce, ed3, 1.0f), acc.w);
    }
    if (w > 0) part[w - 1][lane] = acc;
    __syncthreads();
    if (w == 0) {
        float4 p0 = part[0][lane], p1 = part[1][lane], p2 = part[2][lane];
        acc.x += p0.x + p1.x + p2.x;
        acc.y += p0.y + p1.y + p2.y;
        acc.z += p0.z + p1.z + p2.z;
        acc.w += p0.w + p1.w + p2.w;
        *(float4*)&g_u[b * DIM + d0] = acc;
    }
}

// ---------------- one hop (overlaps the gather stream) ------------------------
__global__ __launch_bounds__(512, 1)
void hop_kernel(int h, const float* __restrict__ Tw, const float* __restrict__ Tb) {
    __shared__ float  u_sh[DIM];
    __shared__ float  prob[MEMSZ];
    __shared__ float  red[512];
    __shared__ float4 opart[16][32];
    __shared__ float  o_sh[DIM];

    int b    = blockIdx.x;
    int tid  = threadIdx.x;
    int lane = tid & 31, w = tid >> 5;       // 16 warps

    if (tid < DIM) u_sh[tid] = g_u[b * DIM + tid];
    __syncthreads();

    const float* mA = g_m + ((ll)h * BATCH * MEMSZ + (ll)b * MEMSZ) * DIM;
    const float* mC = mA + (ll)BATCH * MEMSZ * DIM;

    float4 us = *(const float4*)&u_sh[lane * 4];
    for (int m = w; m < MEMSZ; m += 16) {
        float4 v = __ldg((const float4*)&mA[(ll)m * DIM + lane * 4]);
        float s = v.x * us.x + v.y * us.y + v.z * us.z + v.w * us.w;
#pragma unroll
        for (int off = 16; off; off >>= 1) s += __shfl_xor_sync(0xffffffffu, s, off);
        if (lane == 0) prob[m] = s;
    }
    __syncthreads();

    float4 r[13];
#pragma unroll
    for (int i = 0; i < 13; ++i) {
        int m = w + i * 16;
        if (m < MEMSZ) r[i] = __ldg((const float4*)&mC[(ll)m * DIM + lane * 4]);
    }

    if (tid < 32) {
        float v[7];
        float mx = -1e30f;
#pragma unroll
        for (int j = 0; j < 7; ++j) {
            int m = tid + j * 32;
            v[j] = (m < MEMSZ) ? prob[m] : -1e30f;
            mx = fmaxf(mx, v[j]);
        }
#pragma unroll
        for (int off = 16; off; off >>= 1)
            mx = fmaxf(mx, __shfl_xor_sync(0xffffffffu, mx, off));
        float sum = 0.0f;
#pragma unroll
        for (int j = 0; j < 7; ++j) { v[j] = expf(v[j] - mx); sum += v[j]; }
#pragma unroll
        for (int off = 16; off; off >>= 1)
            sum += __shfl_xor_sync(0xffffffffu, sum, off);
        float inv = 1.0f / sum;
#pragma unroll
        for (int j = 0; j < 7; ++j) {
            int m = tid + j * 32;
            if (m < MEMSZ) prob[m] = v[j] * inv;
        }
    }
    __syncthreads();

    float4 o = make_float4(0.f, 0.f, 0.f, 0.f);
#pragma unroll
    for (int i = 0; i < 13; ++i) {
        int m = w + i * 16;
        if (m < MEMSZ) {
            float p = prob[m];
            o.x = fmaf(p, r[i].x, o.x); o.y = fmaf(p, r[i].y, o.y);
            o.z = fmaf(p, r[i].z, o.z); o.w = fmaf(p, r[i].w, o.w);
        }
    }
    opart[w][lane] = o;
    __syncthreads();
    if (tid < 32) {
        float4 s = make_float4(0.f, 0.f, 0.f, 0.f);
#pragma unroll
        for (int ww = 0; ww < 16; ++ww) {
            float4 p = opart[ww][tid];
            s.x += p.x; s.y += p.y; s.z += p.z; s.w += p.w;
        }
        *(float4*)&o_sh[tid * 4] = s;
    }
    __syncthreads();

    {
        int d = tid >> 2, q = tid & 3;
        const float* twrow = Tw + (ll)d * DIM + q * 32;
        float part = 0.0f;
#pragma unroll
        for (int j = 0; j < 32; j += 4) {
            float4 tv = __ldg((const float4*)&twrow[j]);
            float4 uv = *(const float4*)&u_sh[q * 32 + j];
            part = fmaf(tv.x, uv.x, part); part = fmaf(tv.y, uv.y, part);
            part = fmaf(tv.z, uv.z, part); part = fmaf(tv.w, uv.w, part);
        }
        red[tid] = part;
    }
    __syncthreads();
    if ((tid & 3) == 0) {
        int d = tid >> 2;
        float t = red[tid] + red[tid + 1] + red[tid + 2] + red[tid + 3] + __ldg(&Tb[d]);
        t = 1.0f / (1.0f + expf(-t));
        float un = (1.0f - t) * u_sh[d] + o_sh[d] * t;
        g_u[b * DIM + d] = un;
        if (h == HOPS - 1) g_uh[b * DIM + d] = __float2half(un);
    }
}

// ---------------- a_hat[b,v] = sum_d u[b,d]*C3[v,d] via wmma fp16 -------------
// Loads C3 in fp32, converts to fp16 in registers while staging to smem.
__global__ __launch_bounds__(256, 2)
void out_gemm(const float* __restrict__ C3, float* __restrict__ out) {
    extern __shared__ __half sh[];
    __half* As = sh;                 // C3 tile as fp16 [128][128]
    __half* Bs = sh + 128 * 128;     // uh            [128][128]

    int tid = threadIdx.x;
    int wid = tid >> 5;
    int v0  = blockIdx.x * 128;

    for (int i = tid; i < 128 * 32; i += 256) {
        int row = i >> 5, seg = i & 31;
        if (v0 + row < VOCAB) {
            float4 f = __ldg((const float4*)&C3[(ll)(v0 + row) * DIM + seg * 4]);
            __half2 h0 = __floats2half2_rn(f.x, f.y);
            __half2 h1 = __floats2half2_rn(f.z, f.w);
            uint2 st;
            st.x = *(unsigned*)&h0; st.y = *(unsigned*)&h1;
            *(uint2*)&As[row * 128 + seg * 4] = st;
        }
    }
    for (int i = tid; i < 128 * 16; i += 256)
        ((uint4*)Bs)[i] = __ldg(((const uint4*)g_uh) + i);
    __syncthreads();

    wmma::fragment<wmma::accumulator, 16, 16, 16, float> acc[8];
#pragma unroll
    for (int n = 0; n < 8; ++n) wmma::fill_fragment(acc[n], 0.0f);

#pragma unroll
    for (int kt = 0; kt < 8; ++kt) {
        wmma::fragment<wmma::matrix_a, 16, 16, 16, __half, wmma::row_major> af;
        wmma::load_matrix_sync(af, As + (wid * 16) * 128 + kt * 16, 128);
#pragma unroll
        for (int n = 0; n < 8; ++n) {
            wmma::fragment<wmma::matrix_b, 16, 16, 16, __half, wmma::col_major> bf;
            wmma::load_matrix_sync(bf, Bs + (n * 16) * 128 + kt * 16, 128);
            wmma::mma_sync(acc[n], af, bf, acc[n]);
        }
    }

    if (v0 + wid * 16 + 16 <= VOCAB) {
#pragma unroll
        for (int n = 0; n < 8; ++n)
            wmma::store_matrix_sync(out + (ll)(n * 16) * VOCAB + v0 + wid * 16,
                                    acc[n], VOCAB, wmma::mem_col_major);
    }
}

// ---------------- launch: fork-join DAG ---------------------------------------
extern "C" void kernel_launch(void* const* d_in, const int* in_sizes, int n_in,
                              void* d_out, int out_size) {
    const void*  story = d_in[0];                 // [B,M,S] int32 or int64
    const void*  query = d_in[1];                 // [B,S]
    const float* C     = (const float*)d_in[2];   // [4,V,D]
    const float* Tw    = (const float*)d_in[3];   // [D,D]
    const float* Tb    = (const float*)d_in[4];   // [D]
    float* out = (float*)d_out;                   // [B,V]

    cudaFuncSetAttribute(out_gemm, cudaFuncAttributeMaxDynamicSharedMemorySize,
                         2 * 128 * 128 * (int)sizeof(__half));

    cudaStream_t s1;
    cudaStreamCreateWithFlags(&s1, cudaStreamNonBlocking);
    cudaEvent_t ef, e1, e2, e3, ej;
    cudaEventCreateWithFlags(&ef, cudaEventDisableTiming);
    cudaEventCreateWithFlags(&e1, cudaEventDisableTiming);
    cudaEventCreateWithFlags(&e2, cudaEventDisableTiming);
    cudaEventCreateWithFlags(&e3, cudaEventDisableTiming);
    cudaEventCreateWithFlags(&ej, cudaEventDisableTiming);

    float* g_m_ptr;
    cudaGetSymbolAddress((void**)&g_m_ptr, g_m);
    const int NBM = (BATCH * MEMSZ) / 2;          // 12800 blocks (2 bm each)

    // main stream: sniff -> gathers (tables 0+1 fused, then 2, then 3)
    sniff_kernel<<<1, 256>>>((const int*)story, in_sizes[0]);
    cudaEventRecord(ef, 0);
    cudaStreamWaitEvent(s1, ef, 0);                 // fork

    // side stream: u0 overlaps the first gather
    u0_kernel<<<BATCH, 128, 0, s1>>>(query, C);

    m_kernel<<<dim3(NBM, 2), 256>>>(story, C, 0, g_m_ptr);   // tables 0,1
    cudaEventRecord(e1, 0);                         // m0,m1 ready
    m_kernel<<<dim3(NBM, 1), 256>>>(story, C, 2, g_m_ptr);   // table 2
    cudaEventRecord(e2, 0);                         // m2 ready
    m_kernel<<<dim3(NBM, 1), 256>>>(story, C, 3, g_m_ptr);   // table 3
    cudaEventRecord(e3, 0);                         // m3 ready

    // side stream: hops fire as their tables land
    cudaStreamWaitEvent(s1, e1, 0);
    hop_kernel<<<BATCH, 512, 0, s1>>>(0, Tw, Tb);   // overlaps table-2 gather
    cudaStreamWaitEvent(s1, e2, 0);
    hop_kernel<<<BATCH, 512, 0, s1>>>(1, Tw, Tb);   // overlaps table-3 gather
    cudaStreamWaitEvent(s1, e3, 0);
    hop_kernel<<<BATCH, 512, 0, s1>>>(2, Tw, Tb);

    out_gemm<<<(VOCAB + 127) / 128, 256, 2 * 128 * 128 * sizeof(__half), s1>>>(
        C + 3ll * VOCAB * DIM, out);

    cudaEventRecord(ej, s1);
    cudaStreamWaitEvent(0, ej, 0);                  // join
}

// round 17
// speedup vs baseline: 1.3516x; 1.0033x over previous
#include <cuda_runtime.h>
#include <cuda_fp16.h>
#include <mma.h>
#include <cstdint>

using namespace nvcuda;

#define BATCH 128
#define MEMSZ 200
#define SENT  50
#define DIM   128
#define VOCAB 50000
#define HOPS  3

typedef long long ll;

// ---------------- scratch (device globals) ------------------------------------
__device__ float  g_m[4ll * BATCH * MEMSZ * DIM];    // m_k for tables 0..3 (fp32)
__device__ float  g_u[BATCH * DIM];                  // u between hops (fp32)
__device__ __half g_uh[BATCH * DIM];                 // final u in fp16
__device__ int    g_is64;

__device__ __forceinline__ int load_idx(const void* p, ll i, int is64) {
    if (is64) return (int)__ldg(((const ll*)p) + i);
    return __ldg(((const int*)p) + i);
}

// ---------------- dtype sniff -------------------------------------------------
__global__ void sniff_kernel(const int* __restrict__ story32, int n32) {
    __shared__ int any;
    if (threadIdx.x == 0) any = 0;
    __syncthreads();
    int lim = n32 < 4001 ? n32 : 4001;
    int local = 0;
    for (int i = 1 + 2 * (int)threadIdx.x; i < lim; i += 2 * (int)blockDim.x)
        local |= __ldg(&story32[i]);
    if (local) atomicOr(&any, 1);
    __syncthreads();
    if (threadIdx.x == 0) g_is64 = (any == 0) ? 1 : 0;
}

// ---------------- m_k[b,m,d] = sum_s C_k[story[b,m,s]][d] * enc(s,d) ----------
// fp32 gather — LTS-capped (R12 shape: 128 thr, 1 bm/block). bm0 allows
// batch-half splits of a pass.
__global__ void m_kernel(const void* __restrict__ story, const float* __restrict__ tab,
                         float* __restrict__ mout, int bm0) {
    int bm   = bm0 + blockIdx.x;
    int tid  = threadIdx.x;
    int lane = tid & 31, w = tid >> 5;

    __shared__ int    s_off[SENT];          // byte offset into table
    __shared__ float4 part[3][32];

    int is64 = g_is64;
    if (tid < SENT)
        s_off[tid] = load_idx(story, (ll)bm * SENT + tid, is64) * (DIM * 4);
    __syncthreads();

    const int d0 = lane * 4;
    const float cc  = 4.0f / ((float)DIM * (float)SENT);
    const float ed0 = (float)(d0 + 1) - 64.5f;
    const float ed1 = ed0 + 1.0f, ed2 = ed0 + 2.0f, ed3 = ed0 + 3.0f;
    const char* base = (const char*)tab;

    float4 acc = make_float4(0.f, 0.f, 0.f, 0.f);
    for (int s = w; s < SENT; s += 4) {
        float es = (s == SENT - 1) ? 0.0f : ((float)(s + 1) - 25.5f);
        float ce = cc * es;
        float4 v = ((const float4*)(base + s_off[s]))[lane];
        acc.x = fmaf(v.x, fmaf(ce, ed0, 1.0f), acc.x);
        acc.y = fmaf(v.y, fmaf(ce, ed1, 1.0f), acc.y);
        acc.z = fmaf(v.z, fmaf(ce, ed2, 1.0f), acc.z);
        acc.w = fmaf(v.w, fmaf(ce, ed3, 1.0f), acc.w);
    }
    if (w > 0) part[w - 1][lane] = acc;
    __syncthreads();
    if (w == 0) {
        float4 p0 = part[0][lane], p1 = part[1][lane], p2 = part[2][lane];
        acc.x += p0.x + p1.x + p2.x;
        acc.y += p0.y + p1.y + p2.y;
        acc.z += p0.z + p1.z + p2.z;
        acc.w += p0.w + p1.w + p2.w;
        *(float4*)&mout[(ll)bm * DIM + d0] = acc;
    }
}

// ---------------- u0[b,d] = sum_s C0[query[b,s]][d] * enc(s,d) ---------------
__global__ void u0_kernel(const void* __restrict__ query, const float* __restrict__ C) {
    int b    = blockIdx.x;
    int tid  = threadIdx.x;
    int lane = tid & 31, w = tid >> 5;

    __shared__ int    s_idx[SENT];
    __shared__ float4 part[3][32];

    int is64 = g_is64;
    if (tid < SENT) s_idx[tid] = load_idx(query, (ll)b * SENT + tid, is64);
    __syncthreads();

    const int d0 = lane * 4;
    const float cc  = 4.0f / ((float)DIM * (float)SENT);
    const float ed0 = (float)(d0 + 1) - 64.5f;
    const float ed1 = ed0 + 1.0f, ed2 = ed0 + 2.0f, ed3 = ed0 + 3.0f;

    float4 acc = make_float4(0.f, 0.f, 0.f, 0.f);
    for (int s = w; s < SENT; s += 4) {
        float es = (s == SENT - 1) ? 0.0f : ((float)(s + 1) - 25.5f);
        float ce = cc * es;
        float4 v = __ldg((const float4*)&C[(ll)s_idx[s] * DIM + d0]);
        acc.x = fmaf(v.x, fmaf(ce, ed0, 1.0f), acc.x);
        acc.y = fmaf(v.y, fmaf(ce, ed1, 1.0f), acc.y);
        acc.z = fmaf(v.z, fmaf(ce, ed2, 1.0f), acc.z);
        acc.w = fmaf(v.w, fmaf(ce, ed3, 1.0f), acc.w);
    }
    if (w > 0) part[w - 1][lane] = acc;
    __syncthreads();
    if (w == 0) {
        float4 p0 = part[0][lane], p1 = part[1][lane], p2 = part[2][lane];
        acc.x += p0.x + p1.x + p2.x;
        acc.y += p0.y + p1.y + p2.y;
        acc.z += p0.z + p1.z + p2.z;
        acc.w += p0.w + p1.w + p2.w;
        *(float4*)&g_u[b * DIM + d0] = acc;
    }
}

// ---------------- one hop (b0 allows batch-half splits) -----------------------
__global__ __launch_bounds__(512, 1)
void hop_kernel(int h, int b0, const float* __restrict__ Tw, const float* __restrict__ Tb) {
    __shared__ float  u_sh[DIM];
    __shared__ float  prob[MEMSZ];
    __shared__ float  red[512];
    __shared__ float4 opart[16][32];
    __shared__ float  o_sh[DIM];

    int b    = b0 + blockIdx.x;
    int tid  = threadIdx.x;
    int lane = tid & 31, w = tid >> 5;       // 16 warps

    if (tid < DIM) u_sh[tid] = g_u[b * DIM + tid];
    __syncthreads();

    const float* mA = g_m + ((ll)h * BATCH * MEMSZ + (ll)b * MEMSZ) * DIM;
    const float* mC = mA + (ll)BATCH * MEMSZ * DIM;

    float4 us = *(const float4*)&u_sh[lane * 4];
    for (int m = w; m < MEMSZ; m += 16) {
        float4 v = __ldg((const float4*)&mA[(ll)m * DIM + lane * 4]);
        float s = v.x * us.x + v.y * us.y + v.z * us.z + v.w * us.w;
#pragma unroll
        for (int off = 16; off; off >>= 1) s += __shfl_xor_sync(0xffffffffu, s, off);
        if (lane == 0) prob[m] = s;
    }
    __syncthreads();

    float4 r[13];
#pragma unroll
    for (int i = 0; i < 13; ++i) {
        int m = w + i * 16;
        if (m < MEMSZ) r[i] = __ldg((const float4*)&mC[(ll)m * DIM + lane * 4]);
    }

    if (tid < 32) {
        float v[7];
        float mx = -1e30f;
#pragma unroll
        for (int j = 0; j < 7; ++j) {
            int m = tid + j * 32;
            v[j] = (m < MEMSZ) ? prob[m] : -1e30f;
            mx = fmaxf(mx, v[j]);
        }
#pragma unroll
        for (int off = 16; off; off >>= 1)
            mx = fmaxf(mx, __shfl_xor_sync(0xffffffffu, mx, off));
        float sum = 0.0f;
#pragma unroll
        for (int j = 0; j < 7; ++j) { v[j] = expf(v[j] - mx); sum += v[j]; }
#pragma unroll
        for (int off = 16; off; off >>= 1)
            sum += __shfl_xor_sync(0xffffffffu, sum, off);
        float inv = 1.0f / sum;
#pragma unroll
        for (int j = 0; j < 7; ++j) {
            int m = tid + j * 32;
            if (m < MEMSZ) prob[m] = v[j] * inv;
        }
    }
    __syncthreads();

    float4 o = make_float4(0.f, 0.f, 0.f, 0.f);
#pragma unroll
    for (int i = 0; i < 13; ++i) {
        int m = w + i * 16;
        if (m < MEMSZ) {
            float p = prob[m];
            o.x = fmaf(p, r[i].x, o.x); o.y = fmaf(p, r[i].y, o.y);
            o.z = fmaf(p, r[i].z, o.z); o.w = fmaf(p, r[i].w, o.w);
        }
    }
    opart[w][lane] = o;
    __syncthreads();
    if (tid < 32) {
        float4 s = make_float4(0.f, 0.f, 0.f, 0.f);
#pragma unroll
        for (int ww = 0; ww < 16; ++ww) {
            float4 p = opart[ww][tid];
            s.x += p.x; s.y += p.y; s.z += p.z; s.w += p.w;
        }
        *(float4*)&o_sh[tid * 4] = s;
    }
    __syncthreads();

    {
        int d = tid >> 2, q = tid & 3;
        const float* twrow = Tw + (ll)d * DIM + q * 32;
        float part = 0.0f;
#pragma unroll
        for (int j = 0; j < 32; j += 4) {
            float4 tv = __ldg((const float4*)&twrow[j]);
            float4 uv = *(const float4*)&u_sh[q * 32 + j];
            part = fmaf(tv.x, uv.x, part); part = fmaf(tv.y, uv.y, part);
            part = fmaf(tv.z, uv.z, part); part = fmaf(tv.w, uv.w, part);
        }
        red[tid] = part;
    }
    __syncthreads();
    if ((tid & 3) == 0) {
        int d = tid >> 2;
        float t = red[tid] + red[tid + 1] + red[tid + 2] + red[tid + 3] + __ldg(&Tb[d]);
        t = 1.0f / (1.0f + expf(-t));
        float un = (1.0f - t) * u_sh[d] + o_sh[d] * t;
        g_u[b * DIM + d] = un;
        if (h == HOPS - 1) g_uh[b * DIM + d] = __float2half(un);
    }
}

// ---------------- a_hat[b0..b0+63][v] = u @ C3^T via wmma fp16 ----------------
// Half-batch gemm: 64 b rows per call, C3 fp32->fp16 converted while staging.
// smem = 32KB (As) + 16KB (Bs) = 48KB.
__global__ __launch_bounds__(256, 2)
void out_gemm(const float* __restrict__ C3, float* __restrict__ out, int b0) {
    extern __shared__ __half sh[];
    __half* As = sh;                 // C3 tile as fp16 [128][128]
    __half* Bs = sh + 128 * 128;     // uh half-batch  [64][128]

    int tid = threadIdx.x;
    int wid = tid >> 5;
    int v0  = blockIdx.x * 128;

    for (int i = tid; i < 128 * 32; i += 256) {
        int row = i >> 5, seg = i & 31;
        if (v0 + row < VOCAB) {
            float4 f = __ldg((const float4*)&C3[(ll)(v0 + row) * DIM + seg * 4]);
            __half2 h0 = __floats2half2_rn(f.x, f.y);
            __half2 h1 = __floats2half2_rn(f.z, f.w);
            uint2 st;
            st.x = *(unsigned*)&h0; st.y = *(unsigned*)&h1;
            *(uint2*)&As[row * 128 + seg * 4] = st;
        }
    }
    for (int i = tid; i < 64 * 16; i += 256)
        ((uint4*)Bs)[i] = __ldg(((const uint4*)g_uh) + b0 * 16 + i);
    __syncthreads();

    wmma::fragment<wmma::accumulator, 16, 16, 16, float> acc[4];
#pragma unroll
    for (int n = 0; n < 4; ++n) wmma::fill_fragment(acc[n], 0.0f);

#pragma unroll
    for (int kt = 0; kt < 8; ++kt) {
        wmma::fragment<wmma::matrix_a, 16, 16, 16, __half, wmma::row_major> af;
        wmma::load_matrix_sync(af, As + (wid * 16) * 128 + kt * 16, 128);
#pragma unroll
        for (int n = 0; n < 4; ++n) {
            wmma::fragment<wmma::matrix_b, 16, 16, 16, __half, wmma::col_major> bf;
            wmma::load_matrix_sync(bf, Bs + (n * 16) * 128 + kt * 16, 128);
            wmma::mma_sync(acc[n], af, bf, acc[n]);
        }
    }

    if (v0 + wid * 16 + 16 <= VOCAB) {
#pragma unroll
        for (int n = 0; n < 4; ++n)
            wmma::store_matrix_sync(out + (ll)(b0 + n * 16) * VOCAB + v0 + wid * 16,
                                    acc[n], VOCAB, wmma::mem_col_major);
    }
}

// ---------------- launch: fork-join DAG with split tail -----------------------
extern "C" void kernel_launch(void* const* d_in, const int* in_sizes, int n_in,
                              void* d_out, int out_size) {
    const void*  story = d_in[0];                 // [B,M,S] int32 or int64
    const void*  query = d_in[1];                 // [B,S]
    const float* C     = (const float*)d_in[2];   // [4,V,D]
    const float* Tw    = (const float*)d_in[3];   // [D,D]
    const float* Tb    = (const float*)d_in[4];   // [D]
    float* out = (float*)d_out;                   // [B,V]

    const int GEMM_SMEM = (128 * 128 + 64 * 128) * (int)sizeof(__half);   // 48KB
    cudaFuncSetAttribute(out_gemm, cudaFuncAttributeMaxDynamicSharedMemorySize,
                         GEMM_SMEM);

    cudaStream_t s1;
    cudaStreamCreateWithFlags(&s1, cudaStreamNonBlocking);
    cudaEvent_t ef, e1, e2, e3a, e3b, ej;
    cudaEventCreateWithFlags(&ef,  cudaEventDisableTiming);
    cudaEventCreateWithFlags(&e1,  cudaEventDisableTiming);
    cudaEventCreateWithFlags(&e2,  cudaEventDisableTiming);
    cudaEventCreateWithFlags(&e3a, cudaEventDisableTiming);
    cudaEventCreateWithFlags(&e3b, cudaEventDisableTiming);
    cudaEventCreateWithFlags(&ej,  cudaEventDisableTiming);

    float* g_m_ptr;
    cudaGetSymbolAddress((void**)&g_m_ptr, g_m);
    const ll MSTR = (ll)BATCH * MEMSZ * DIM;
    const int NBM  = BATCH * MEMSZ;           // 25600
    const int HALF = NBM / 2;                 // 12800 (= batches 0..63)

    // main stream: sniff -> gathers 0,1,2, then table 3 in two batch halves
    sniff_kernel<<<1, 256>>>((const int*)story, in_sizes[0]);
    cudaEventRecord(ef, 0);
    cudaStreamWaitEvent(s1, ef, 0);                 // fork

    u0_kernel<<<BATCH, 128, 0, s1>>>(query, C);     // overlaps gather pass 0

    m_kernel<<<NBM, 128>>>(story, C + 0ll * VOCAB * DIM, g_m_ptr + 0 * MSTR, 0);
    m_kernel<<<NBM, 128>>>(story, C + 1ll * VOCAB * DIM, g_m_ptr + 1 * MSTR, 0);
    cudaEventRecord(e1, 0);                         // m0,m1 ready
    m_kernel<<<NBM, 128>>>(story, C + 2ll * VOCAB * DIM, g_m_ptr + 2 * MSTR, 0);
    cudaEventRecord(e2, 0);                         // m2 ready
    m_kernel<<<HALF, 128>>>(story, C + 3ll * VOCAB * DIM, g_m_ptr + 3 * MSTR, 0);
    cudaEventRecord(e3a, 0);                        // m3 (b 0..63) ready
    m_kernel<<<HALF, 128>>>(story, C + 3ll * VOCAB * DIM, g_m_ptr + 3 * MSTR, HALF);
    cudaEventRecord(e3b, 0);                        // m3 (b 64..127) ready

    // side stream: hops/gemm fire as their data lands
    cudaStreamWaitEvent(s1, e1, 0);
    hop_kernel<<<BATCH, 512, 0, s1>>>(0, 0, Tw, Tb);        // overlaps m2 gather
    cudaStreamWaitEvent(s1, e2, 0);
    hop_kernel<<<BATCH, 512, 0, s1>>>(1, 0, Tw, Tb);        // overlaps m3 gathers
    cudaStreamWaitEvent(s1, e3a, 0);
    hop_kernel<<<BATCH / 2, 512, 0, s1>>>(2, 0, Tw, Tb);    // b 0..63, overlaps m3b
    out_gemm<<<(VOCAB + 127) / 128, 256, GEMM_SMEM, s1>>>(
        C + 3ll * VOCAB * DIM, out, 0);                     // b 0..63, overlaps m3b
    cudaStreamWaitEvent(s1, e3b, 0);
    hop_kernel<<<BATCH / 2, 512, 0, s1>>>(2, BATCH / 2, Tw, Tb);   // b 64..127
    out_gemm<<<(VOCAB + 127) / 128, 256, GEMM_SMEM, s1>>>(
        C + 3ll * VOCAB * DIM, out, BATCH / 2);

    cudaEventRecord(ej, s1);
    cudaStreamWaitEvent(0, ej, 0);                  // join
}